// round 7
// baseline (speedup 1.0000x reference)
#include <cuda_runtime.h>
#include <math.h>
#include <stdint.h>

#define BB    32
#define LL1   64
#define LL2   64
#define HH    256
#define FEATF 512

// Scratch: K-split partial outputs (a: k=[0,256), b: k=[256,512))
__device__ float g_y1a[BB * LL1 * HH];
__device__ float g_y1b[BB * LL1 * HH];
__device__ float g_y2a[BB * LL2 * HH];
__device__ float g_y2b[BB * LL2 * HH];
__device__ float g_part[4 * BB * HH];     // pairsum partials [s][b][h]

// ---------------------------------------------------------------------------
// GEMM via mma.sync tf32 — aux-issue-minimized version.
// Grid (64 mT, 4 nT, 2 kS) = 512 CTAs x 8 warps (4m x 2n), warp tile 16x32.
// SMEM layout scattered by k%4 so fragment loads are LDS.128:
//   sm[row][t][j] = tf32(X[row][j*4+t]),  row stride 36 (4-phase conflict-free)
// Conversion to tf32 happens ONCE at fill; consumers feed raw bits to MMA.
// Register prefetch 2 chunks ahead (no cp.async — fill needs cvt).
// ---------------------------------------------------------------------------
#define TKC   32
#define ROWSTR 36                     // floats per row (32 data + 4 pad)
#define TILEWORDS (64 * ROWSTR)       // 2304 words per operand tile

__device__ __forceinline__ uint32_t f2tf32(float f) {
    uint32_t r;
    asm("cvt.rna.tf32.f32 %0, %1;" : "=r"(r) : "f"(f));
    return r;
}
__device__ __forceinline__ void mma_tf32(float* c, const uint32_t* a,
                                         uint32_t b0, uint32_t b1) {
    asm volatile(
        "mma.sync.aligned.m16n8k8.row.col.f32.tf32.tf32.f32 "
        "{%0,%1,%2,%3}, {%4,%5,%6,%7}, {%8,%9}, {%0,%1,%2,%3};"
        : "+f"(c[0]), "+f"(c[1]), "+f"(c[2]), "+f"(c[3])
        : "r"(a[0]), "r"(a[1]), "r"(a[2]), "r"(a[3]), "r"(b0), "r"(b1));
}

__global__ void __launch_bounds__(256, 2)
gemm_mma(const float* __restrict__ x1, const float* __restrict__ x2,
         const float* __restrict__ W)
{
    __shared__ __align__(16) uint32_t sm[2 * TILEWORDS];   // A tile then B tile

    const int tid = threadIdx.x;
    const int wid = tid >> 5, lane = tid & 31;
    const int g = lane >> 2, t = lane & 3;

    const int mT = blockIdx.x;              // 0..63
    const int nT = blockIdx.y;              // 0..3
    const int kS = blockIdx.z;              // 0..1
    const int half = (mT >= 32) ? 1 : 0;
    const float* __restrict__ X = half ? x2 : x1;
    const int rowLoc = (mT & 31) * 64;
    const int hBase  = nT * 64;
    const int kOff   = kS * 256;
    const int wOff   = (half ? FEATF : 0) + kOff;

    const int mW = (wid & 3) * 16;          // warp m offset: 0,16,32,48
    const int nW = (wid >> 2) * 32;         // warp n offset: 0,32

    // ---- fill indexing: thread covers rows r, r+32 of A and B, seg sg ----
    const int r  = tid >> 3;                // 0..31
    const int sg = tid & 7;                 // float4 segment within 32-k chunk
    const float* gA = X + (size_t)(rowLoc + r) * FEATF + kOff + sg * 4;
    const float* gB = W + (size_t)(hBase + r) * (4 * HH) + wOff + sg * 4;
    const size_t gAs = (size_t)32 * FEATF;      // row+32 stride
    const size_t gBs = (size_t)32 * (4 * HH);

    float4 pa0[2], pa1[2], pb0[2], pb1[2];  // 2-deep prefetch sets

    auto fetch = [&](int c, int s) {
        pa0[s] = *(const float4*)(gA + c * TKC);
        pa1[s] = *(const float4*)(gA + c * TKC + gAs);
        pb0[s] = *(const float4*)(gB + c * TKC);
        pb1[s] = *(const float4*)(gB + c * TKC + gBs);
    };
    auto scatter = [&](int s) {
        // dst word = row*ROWSTR + e*8 + sg  (e = k%4, j = k/4 = sg)
        uint32_t* dA0 = sm + r * ROWSTR + sg;
        uint32_t* dA1 = dA0 + 32 * ROWSTR;
        uint32_t* dB0 = sm + TILEWORDS + r * ROWSTR + sg;
        uint32_t* dB1 = dB0 + 32 * ROWSTR;
        const float* a0 = (const float*)&pa0[s];
        const float* a1 = (const float*)&pa1[s];
        const float* b0 = (const float*)&pb0[s];
        const float* b1 = (const float*)&pb1[s];
        #pragma unroll
        for (int e = 0; e < 4; e++) {
            dA0[e * 8] = f2tf32(a0[e]);
            dA1[e * 8] = f2tf32(a1[e]);
            dB0[e * 8] = f2tf32(b0[e]);
            dB1[e * 8] = f2tf32(b1[e]);
        }
    };

    float acc[4][4];
    #pragma unroll
    for (int nf = 0; nf < 4; nf++)
        #pragma unroll
        for (int q = 0; q < 4; q++) acc[nf][q] = 0.0f;

    // frag base addresses (constant across chunks)
    const uint32_t* Ar0 = sm + (mW + g) * ROWSTR + t * 8;
    const uint32_t* Ar1 = Ar0 + 8 * ROWSTR;
    const uint32_t* Bb  = sm + TILEWORDS + (nW + g) * ROWSTR + t * 8;

    fetch(0, 0);
    fetch(1, 1);

    #pragma unroll 1
    for (int c = 0; c < 8; c++) {
        if (c) __syncthreads();             // all warps done with smem chunk c-1
        scatter(c & 1);
        __syncthreads();
        if (c + 2 < 8) fetch(c + 2, c & 1);

        // fragment loads: 12 x LDS.128 covering all 4 k8-steps of this chunk
        uint4 a0l = *(const uint4*)(Ar0);
        uint4 a0h = *(const uint4*)(Ar0 + 4);
        uint4 a1l = *(const uint4*)(Ar1);
        uint4 a1h = *(const uint4*)(Ar1 + 4);
        uint4 bl[4], bh[4];
        #pragma unroll
        for (int nf = 0; nf < 4; nf++) {
            bl[nf] = *(const uint4*)(Bb + nf * 8 * ROWSTR);
            bh[nf] = *(const uint4*)(Bb + nf * 8 * ROWSTR + 4);
        }

        {   // q = 0
            uint32_t a[4] = {a0l.x, a1l.x, a0l.y, a1l.y};
            #pragma unroll
            for (int nf = 0; nf < 4; nf++) mma_tf32(acc[nf], a, bl[nf].x, bl[nf].y);
        }
        {   // q = 1
            uint32_t a[4] = {a0l.z, a1l.z, a0l.w, a1l.w};
            #pragma unroll
            for (int nf = 0; nf < 4; nf++) mma_tf32(acc[nf], a, bl[nf].z, bl[nf].w);
        }
        {   // q = 2
            uint32_t a[4] = {a0h.x, a1h.x, a0h.y, a1h.y};
            #pragma unroll
            for (int nf = 0; nf < 4; nf++) mma_tf32(acc[nf], a, bh[nf].x, bh[nf].y);
        }
        {   // q = 3
            uint32_t a[4] = {a0h.z, a1h.z, a0h.w, a1h.w};
            #pragma unroll
            for (int nf = 0; nf < 4; nf++) mma_tf32(acc[nf], a, bh[nf].z, bh[nf].w);
        }
    }

    // Epilogue: direct float2 stores to the K-split half buffer.
    float* __restrict__ Y = half ? (kS ? g_y2b : g_y2a)
                                 : (kS ? g_y1b : g_y1a);
    #pragma unroll
    for (int nf = 0; nf < 4; nf++) {
        const int row = rowLoc + mW + g;
        const int h   = hBase + nW + nf * 8 + 2 * t;
        *(float2*)&Y[(size_t)row * HH + h]       = make_float2(acc[nf][0], acc[nf][1]);
        *(float2*)&Y[(size_t)(row + 8) * HH + h] = make_float2(acc[nf][2], acc[nf][3]);
    }
}

// ---------------------------------------------------------------------------
// Pair reduction (partial over i-chunk of 16). Sums the two K-split halves
// on load; bias folded into t2 here.
// ---------------------------------------------------------------------------
__global__ void __launch_bounds__(256)
pairsum_kernel(const int* __restrict__ sl1p, const int* __restrict__ sl2p,
               const float* __restrict__ bias)
{
    const int b  = blockIdx.y;
    const int hb = blockIdx.x;
    const int s  = blockIdx.z;
    const int tid = threadIdx.x;
    const int h  = tid & 31;
    const int jg = tid >> 5;

    const int sl1 = sl1p[b];
    const int sl2 = sl2p[b];
    const int i0  = s * 16;

    float* part = &g_part[((s * BB + b) * 8 + hb) * 32];
    if (i0 >= sl1) {
        if (tid < 32) part[tid] = 0.0f;
        return;
    }

    __shared__ float y1s[16 * 32];
    {
        int i = tid >> 5, hh = tid & 31;
        int base0 = (b * LL1 + i0 + i)     * HH + hb * 32 + hh;
        int base1 = (b * LL1 + i0 + 8 + i) * HH + hb * 32 + hh;
        y1s[tid]       = g_y1a[base0] + g_y1b[base0];
        y1s[tid + 256] = g_y1a[base1] + g_y1b[base1];
    }
    __syncthreads();

    const float bh = bias[hb * 32 + h];
    float t2[8];
    #pragma unroll
    for (int k = 0; k < 8; k++) {
        int j = jg * 8 + k;
        int idx = (b * LL2 + j) * HH + hb * 32 + h;
        t2[k] = (j < sl2) ? (g_y2a[idx] + g_y2b[idx] + bh) : -INFINITY;
    }

    const int niter = min(16, sl1 - i0);
    float acc[8];
    #pragma unroll
    for (int k = 0; k < 8; k++) acc[k] = 0.0f;

    for (int i = 0; i < niter; i++) {
        float v = y1s[i * 32 + h];
        #pragma unroll
        for (int k = 0; k < 8; k++)
            acc[k] += fmaxf(v + t2[k], 0.0f);
    }

    float p = 0.0f;
    #pragma unroll
    for (int k = 0; k < 8; k++) p += acc[k];

    __shared__ float red[8][32];
    red[jg][h] = p;
    __syncthreads();
    if (jg == 0) {
        float ss = 0.0f;
        #pragma unroll
        for (int gg = 0; gg < 8; gg++) ss += red[gg][h];
        part[h] = ss;
    }
}

// ---------------------------------------------------------------------------
// Final reduce: sum 4 partials, add zero-pad bias term, divide.
// ---------------------------------------------------------------------------
__global__ void __launch_bounds__(256)
reduce_kernel(const int* __restrict__ sl1p, const int* __restrict__ sl2p,
              const float* __restrict__ bias, float* __restrict__ out)
{
    const int b = blockIdx.x;
    const int h = threadIdx.x;
    const int hb = h >> 5, hh = h & 31;
    float ssum = 0.0f;
    #pragma unroll
    for (int st = 0; st < 4; st++)
        ssum += g_part[((st * BB + b) * 8 + hb) * 32 + hh];
    const float n = (float)(sl1p[b] * sl2p[b]);
    const float rb = fmaxf(bias[h], 0.0f);
    out[b * HH + h] = (ssum + ((float)(LL1 * LL2) - n) * rb) / n;
}

extern "C" void kernel_launch(void* const* d_in, const int* in_sizes, int n_in,
                              void* d_out, int out_size)
{
    const float* x1   = (const float*)d_in[0];
    const int*   sl1  = (const int*)  d_in[1];
    const float* x2   = (const float*)d_in[2];
    const int*   sl2  = (const int*)  d_in[3];
    const float* W    = (const float*)d_in[4];
    const float* bias = (const float*)d_in[5];
    float* out = (float*)d_out;

    gemm_mma<<<dim3(64, 4, 2), 256>>>(x1, x2, W);
    pairsum_kernel<<<dim3(8, 32, 4), 256>>>(sl1, sl2, bias);
    reduce_kernel<<<32, 256>>>(sl1, sl2, bias, out);
}

// round 8
// speedup vs baseline: 1.0615x; 1.0615x over previous
#include <cuda_runtime.h>
#include <math.h>
#include <stdint.h>

#define BB    32
#define LL1   64
#define LL2   64
#define HH    256
#define FEATF 512

// K-split partial outputs (a: k=[0,256), b: k=[256,512))
__device__ float g_y1a[BB * LL1 * HH];
__device__ float g_y1b[BB * LL1 * HH];
__device__ float g_y2a[BB * LL2 * HH];
__device__ float g_y2b[BB * LL2 * HH];
__device__ float g_part[4 * BB * HH];

// Pre-converted (tf32 bits), k%4-scattered copies:
// word p within a 32-k chunk holds k = (p&7)*4 + (p>>3)   [e = p>>3, j = p&7]
__device__ uint32_t g_x1t[2048 * FEATF];
__device__ uint32_t g_x2t[2048 * FEATF];
__device__ uint32_t g_Wt[HH * 4 * HH];

__device__ __forceinline__ uint32_t f2tf32(float f) {
    uint32_t r;
    asm("cvt.rna.tf32.f32 %0, %1;" : "=r"(r) : "f"(f));
    return r;
}
__device__ __forceinline__ void mma_tf32(float* c, const uint32_t* a,
                                         uint32_t b0, uint32_t b1) {
    asm volatile(
        "mma.sync.aligned.m16n8k8.row.col.f32.tf32.tf32.f32 "
        "{%0,%1,%2,%3}, {%4,%5,%6,%7}, {%8,%9}, {%0,%1,%2,%3};"
        : "+f"(c[0]), "+f"(c[1]), "+f"(c[2]), "+f"(c[3])
        : "r"(a[0]), "r"(a[1]), "r"(a[2]), "r"(a[3]), "r"(b0), "r"(b1));
}
__device__ __forceinline__ void cp16(uint32_t dst, const void* src) {
    asm volatile("cp.async.cg.shared.global [%0], [%1], 16;" :: "r"(dst), "l"(src));
}
__device__ __forceinline__ uint32_t smem_u32(const void* p) {
    uint32_t a;
    asm("{ .reg .u64 t; cvta.to.shared.u64 t, %1; cvt.u32.u64 %0, t; }"
        : "=r"(a) : "l"(p));
    return a;
}

// ---------------------------------------------------------------------------
// Pre-pass: convert to tf32 bits + permute within each 32-k chunk.
// One word per thread; warp covers exactly one 128B chunk (coalesced).
// ---------------------------------------------------------------------------
#define X_WORDS (2048 * FEATF)          // 1048576 each for x1, x2
#define W_WORDS (HH * 4 * HH)           // 262144
#define PRE_BLOCKS ((2 * X_WORDS + W_WORDS) / 256)

__global__ void __launch_bounds__(256)
preconv_kernel(const float* __restrict__ x1, const float* __restrict__ x2,
               const float* __restrict__ W)
{
    int idx = blockIdx.x * 256 + threadIdx.x;
    const float* src;
    uint32_t* dst;
    int rowlen;
    if (idx < X_WORDS)                 { src = x1; dst = g_x1t; rowlen = FEATF; }
    else if (idx < 2 * X_WORDS)        { src = x2; dst = g_x2t; rowlen = FEATF; idx -= X_WORDS; }
    else                               { src = W;  dst = g_Wt;  rowlen = 4 * HH; idx -= 2 * X_WORDS; }

    const int p  = idx % rowlen;       // position within row
    const int w  = p & 31;             // word within 32-k chunk
    const int c0 = p - w;              // chunk base
    const int k  = c0 + ((w & 7) << 2) + (w >> 3);
    const int rb = idx - p;            // row base
    dst[idx] = f2tf32(src[rb + k]);
}

// ---------------------------------------------------------------------------
// GEMM via mma.sync tf32 — pre-converted operands, LDS.128 fragments, no cvt.
// Grid (64 mT, 4 nT, 2 kS) = 512 CTAs x 8 warps (2m x 2n), warp tile 32x32.
// cp.async double buffer; smem row stride 36 words (conflict-free both sides).
// ---------------------------------------------------------------------------
#define TKC    32
#define ROWSTR 36
#define TILEW  (64 * ROWSTR)           // words per operand stage

__global__ void __launch_bounds__(256)
gemm_mma(int dummy)
{
    __shared__ __align__(16) uint32_t smA[2][TILEW];
    __shared__ __align__(16) uint32_t smB[2][TILEW];

    const int tid = threadIdx.x;
    const int wid = tid >> 5, lane = tid & 31;
    const int g = lane >> 2, t = lane & 3;

    const int mT = blockIdx.x;              // 0..63
    const int nT = blockIdx.y;              // 0..3
    const int kS = blockIdx.z;              // 0..1
    const int half = (mT >= 32) ? 1 : 0;
    const uint32_t* __restrict__ X = half ? g_x2t : g_x1t;
    const int rowLoc = (mT & 31) * 64;
    const int hBase  = nT * 64;
    const int kOff   = kS * 256;
    const int wOff   = (half ? FEATF : 0) + kOff;

    const int mW = (wid & 1) * 32;          // warp m offset: 0,32
    const int nW = (wid >> 1) * 32;         // warp n offset: 0..96 -> but TN=64!
    // 8 warps: 2m x 4n? TN=64 -> n warps 0..3 with warp-n 16? Use 2m x 2n of 32x32
    // over a 64x64 tile: wid bit0 -> m, bit1 -> n, bits2.. replicate k? No:
    // Correct mapping: 8 warps = 2m x 2n x 2k-slices would change math.
    // Instead: 4 warps per (m,n) quadrant is wasteful. Use 2m x 4n with warp
    // tile 32x16: acc[2][2][4]. Simpler: 8 warps = 2m x 4n, warp tile 32x16.
    const int mWq = (wid & 1) * 32;
    const int nWq = (wid >> 1) * 16;        // 0,16,32,48

    // fill mapping: 512 float4-chunks per operand stage; 256 threads x 2
    const int fr = tid >> 2;                // 0..63 row
    const int fs = tid & 3;                 // seg 0..3 (first half of row)
    const uint32_t* gA = X + (size_t)(rowLoc + fr) * FEATF + kOff + fs * 4;
    const uint32_t* gB = g_Wt + (size_t)(hBase + fr) * (4 * HH) + wOff + fs * 4;

    auto load_stage = [&](int s, int c) {
        const uint32_t aB = smem_u32(&smA[s][0]);
        const uint32_t bB = smem_u32(&smB[s][0]);
        const uint32_t dA = aB + (fr * ROWSTR + fs * 4) * 4;
        const uint32_t dB = bB + (fr * ROWSTR + fs * 4) * 4;
        cp16(dA,      gA + c * TKC);
        cp16(dA + 64, gA + c * TKC + 16);    // seg fs+4
        cp16(dB,      gB + c * TKC);
        cp16(dB + 64, gB + c * TKC + 16);
    };

    float acc[2][2][4];                      // [mf][nf][reg], warp tile 32x16
    #pragma unroll
    for (int mf = 0; mf < 2; mf++)
        #pragma unroll
        for (int nf = 0; nf < 2; nf++)
            #pragma unroll
            for (int q = 0; q < 4; q++) acc[mf][nf][q] = 0.0f;

    load_stage(0, 0);
    asm volatile("cp.async.commit_group;" ::: "memory");

    const int NCH = 256 / TKC;               // 8
    for (int c = 0; c < NCH; c++) {
        if (c + 1 < NCH) {
            load_stage((c + 1) & 1, c + 1);
            asm volatile("cp.async.commit_group;" ::: "memory");
            asm volatile("cp.async.wait_group 1;" ::: "memory");
        } else {
            asm volatile("cp.async.wait_group 0;" ::: "memory");
        }
        __syncthreads();

        const int s = c & 1;
        // A rows: mWq+g, +8, +16, +24 ; B rows: nWq+g, nWq+8+g
        const uint32_t* Abase = &smA[s][(mWq + g) * ROWSTR + t * 8];
        const uint32_t* Bbase = &smB[s][(nWq + g) * ROWSTR + t * 8];
        uint4 Alo[4], Ahi[4];
        #pragma unroll
        for (int rr = 0; rr < 4; rr++) {
            Alo[rr] = *(const uint4*)(Abase + rr * 8 * ROWSTR);
            Ahi[rr] = *(const uint4*)(Abase + rr * 8 * ROWSTR + 4);
        }
        uint4 Blo[2], Bhi[2];
        #pragma unroll
        for (int rr = 0; rr < 2; rr++) {
            Blo[rr] = *(const uint4*)(Bbase + rr * 8 * ROWSTR);
            Bhi[rr] = *(const uint4*)(Bbase + rr * 8 * ROWSTR + 4);
        }

        // q = 0: a0=lo.x, a2=lo.y ; b0=lo.x, b1=lo.y
        #pragma unroll
        for (int mf = 0; mf < 2; mf++) {
            uint32_t a[4] = {Alo[2*mf].x, Alo[2*mf+1].x, Alo[2*mf].y, Alo[2*mf+1].y};
            #pragma unroll
            for (int nf = 0; nf < 2; nf++)
                mma_tf32(acc[mf][nf], a, Blo[nf].x, Blo[nf].y);
        }
        // q = 1
        #pragma unroll
        for (int mf = 0; mf < 2; mf++) {
            uint32_t a[4] = {Alo[2*mf].z, Alo[2*mf+1].z, Alo[2*mf].w, Alo[2*mf+1].w};
            #pragma unroll
            for (int nf = 0; nf < 2; nf++)
                mma_tf32(acc[mf][nf], a, Blo[nf].z, Blo[nf].w);
        }
        // q = 2
        #pragma unroll
        for (int mf = 0; mf < 2; mf++) {
            uint32_t a[4] = {Ahi[2*mf].x, Ahi[2*mf+1].x, Ahi[2*mf].y, Ahi[2*mf+1].y};
            #pragma unroll
            for (int nf = 0; nf < 2; nf++)
                mma_tf32(acc[mf][nf], a, Bhi[nf].x, Bhi[nf].y);
        }
        // q = 3
        #pragma unroll
        for (int mf = 0; mf < 2; mf++) {
            uint32_t a[4] = {Ahi[2*mf].z, Ahi[2*mf+1].z, Ahi[2*mf].w, Ahi[2*mf+1].w};
            #pragma unroll
            for (int nf = 0; nf < 2; nf++)
                mma_tf32(acc[mf][nf], a, Bhi[nf].z, Bhi[nf].w);
        }
        __syncthreads();
    }

    float* __restrict__ Y = half ? (kS ? g_y2b : g_y2a)
                                 : (kS ? g_y1b : g_y1a);
    #pragma unroll
    for (int mf = 0; mf < 2; mf++) {
        #pragma unroll
        for (int nf = 0; nf < 2; nf++) {
            const int row = rowLoc + mWq + mf * 16 + g;
            const int h   = hBase + nWq + nf * 8 + 2 * t;
            *(float2*)&Y[(size_t)row * HH + h]       = make_float2(acc[mf][nf][0], acc[mf][nf][1]);
            *(float2*)&Y[(size_t)(row + 8) * HH + h] = make_float2(acc[mf][nf][2], acc[mf][nf][3]);
        }
    }
}

// ---------------------------------------------------------------------------
// Pair reduction (partial over i-chunk of 16); sums K-split halves on load.
// ---------------------------------------------------------------------------
__global__ void __launch_bounds__(256)
pairsum_kernel(const int* __restrict__ sl1p, const int* __restrict__ sl2p,
               const float* __restrict__ bias)
{
    const int b  = blockIdx.y;
    const int hb = blockIdx.x;
    const int s  = blockIdx.z;
    const int tid = threadIdx.x;
    const int h  = tid & 31;
    const int jg = tid >> 5;

    const int sl1 = sl1p[b];
    const int sl2 = sl2p[b];
    const int i0  = s * 16;

    float* part = &g_part[((s * BB + b) * 8 + hb) * 32];
    if (i0 >= sl1) {
        if (tid < 32) part[tid] = 0.0f;
        return;
    }

    __shared__ float y1s[16 * 32];
    {
        int i = tid >> 5, hh = tid & 31;
        int base0 = (b * LL1 + i0 + i)     * HH + hb * 32 + hh;
        int base1 = (b * LL1 + i0 + 8 + i) * HH + hb * 32 + hh;
        y1s[tid]       = g_y1a[base0] + g_y1b[base0];
        y1s[tid + 256] = g_y1a[base1] + g_y1b[base1];
    }
    __syncthreads();

    const float bh = bias[hb * 32 + h];
    float t2[8];
    #pragma unroll
    for (int k = 0; k < 8; k++) {
        int j = jg * 8 + k;
        int idx = (b * LL2 + j) * HH + hb * 32 + h;
        t2[k] = (j < sl2) ? (g_y2a[idx] + g_y2b[idx] + bh) : -INFINITY;
    }

    const int niter = min(16, sl1 - i0);
    float acc[8];
    #pragma unroll
    for (int k = 0; k < 8; k++) acc[k] = 0.0f;

    for (int i = 0; i < niter; i++) {
        float v = y1s[i * 32 + h];
        #pragma unroll
        for (int k = 0; k < 8; k++)
            acc[k] += fmaxf(v + t2[k], 0.0f);
    }

    float p = 0.0f;
    #pragma unroll
    for (int k = 0; k < 8; k++) p += acc[k];

    __shared__ float red[8][32];
    red[jg][h] = p;
    __syncthreads();
    if (jg == 0) {
        float ss = 0.0f;
        #pragma unroll
        for (int gg = 0; gg < 8; gg++) ss += red[gg][h];
        part[h] = ss;
    }
}

__global__ void __launch_bounds__(256)
reduce_kernel(const int* __restrict__ sl1p, const int* __restrict__ sl2p,
              const float* __restrict__ bias, float* __restrict__ out)
{
    const int b = blockIdx.x;
    const int h = threadIdx.x;
    const int hb = h >> 5, hh = h & 31;
    float ssum = 0.0f;
    #pragma unroll
    for (int st = 0; st < 4; st++)
        ssum += g_part[((st * BB + b) * 8 + hb) * 32 + hh];
    const float n = (float)(sl1p[b] * sl2p[b]);
    const float rb = fmaxf(bias[h], 0.0f);
    out[b * HH + h] = (ssum + ((float)(LL1 * LL2) - n) * rb) / n;
}

extern "C" void kernel_launch(void* const* d_in, const int* in_sizes, int n_in,
                              void* d_out, int out_size)
{
    const float* x1   = (const float*)d_in[0];
    const int*   sl1  = (const int*)  d_in[1];
    const float* x2   = (const float*)d_in[2];
    const int*   sl2  = (const int*)  d_in[3];
    const float* W    = (const float*)d_in[4];
    const float* bias = (const float*)d_in[5];
    float* out = (float*)d_out;

    preconv_kernel<<<PRE_BLOCKS, 256>>>(x1, x2, W);
    gemm_mma<<<dim3(64, 4, 2), 256>>>(0);
    pairsum_kernel<<<dim3(8, 32, 4), 256>>>(sl1, sl2, bias);
    reduce_kernel<<<32, 256>>>(sl1, sl2, bias, out);
}

// round 13
// speedup vs baseline: 1.4082x; 1.3265x over previous
#include <cuda_runtime.h>
#include <cuda_fp16.h>
#include <math.h>
#include <stdint.h>

#define BB    32
#define LL1   64
#define LL2   64
#define HH    256
#define FEATF 512

// f16 pre-converted operands
__device__ __half g_x1h[2048 * FEATF];
__device__ __half g_x2h[2048 * FEATF];
__device__ __half g_Wh[HH * 4 * HH];

// K-split partial outputs (a: k=[0,256), b: k=[256,512))
__device__ float g_y1a[BB * LL1 * HH];
__device__ float g_y1b[BB * LL1 * HH];
__device__ float g_y2a[BB * LL2 * HH];
__device__ float g_y2b[BB * LL2 * HH];

__device__ __forceinline__ uint32_t smem_u32(const void* p) {
    uint32_t a;
    asm("{ .reg .u64 t; cvta.to.shared.u64 t, %1; cvt.u32.u64 %0, t; }"
        : "=r"(a) : "l"(p));
    return a;
}
__device__ __forceinline__ void cp16(uint32_t dst, const void* src) {
    asm volatile("cp.async.cg.shared.global [%0], [%1], 16;" :: "r"(dst), "l"(src));
}
__device__ __forceinline__ void ldsm_x4(uint32_t* r, uint32_t addr) {
    asm volatile("ldmatrix.sync.aligned.m8n8.x4.shared.b16 {%0,%1,%2,%3}, [%4];"
                 : "=r"(r[0]), "=r"(r[1]), "=r"(r[2]), "=r"(r[3]) : "r"(addr));
}
__device__ __forceinline__ void mma_f16(float* c, const uint32_t* a,
                                        uint32_t b0, uint32_t b1) {
    asm volatile(
        "mma.sync.aligned.m16n8k16.row.col.f32.f16.f16.f32 "
        "{%0,%1,%2,%3}, {%4,%5,%6,%7}, {%8,%9}, {%0,%1,%2,%3};"
        : "+f"(c[0]), "+f"(c[1]), "+f"(c[2]), "+f"(c[3])
        : "r"(a[0]), "r"(a[1]), "r"(a[2]), "r"(a[3]), "r"(b0), "r"(b1));
}

// ---------------------------------------------------------------------------
// Pre-pass: f32 -> f16 for x1, x2, W (half2 granularity, 4 per thread),
// plus initialization of out with the zero-padding bias term.
// half2 totals: x1 524288, x2 524288, W 131072 => 1179648 = 1152 blocks * 1024.
// ---------------------------------------------------------------------------
__global__ void __launch_bounds__(256)
preconv_kernel(const float* __restrict__ x1, const float* __restrict__ x2,
               const float* __restrict__ W,
               const int* __restrict__ sl1p, const int* __restrict__ sl2p,
               const float* __restrict__ bias, float* __restrict__ out)
{
    const int bid = blockIdx.x;
    if (bid < 1152) {
        #pragma unroll
        for (int q = 0; q < 4; q++) {
            int idx = bid * 1024 + q * 256 + threadIdx.x;
            const float2* s;
            __half2* d;
            int loc;
            if (idx < 524288)        { s = (const float2*)x1; d = (__half2*)g_x1h; loc = idx; }
            else if (idx < 1048576)  { s = (const float2*)x2; d = (__half2*)g_x2h; loc = idx - 524288; }
            else                     { s = (const float2*)W;  d = (__half2*)g_Wh;  loc = idx - 1048576; }
            d[loc] = __float22half2_rn(s[loc]);
        }
    } else {
        // out[b][h] = (4096 - n) * relu(bias[h]) / n
        for (int i = threadIdx.x; i < BB * HH; i += 256) {
            const int b = i >> 8, h = i & 255;
            const float n = (float)(sl1p[b] * sl2p[b]);
            out[i] = ((float)(LL1 * LL2) - n) * fmaxf(bias[h], 0.0f) / n;
        }
    }
}

// ---------------------------------------------------------------------------
// f16 GEMM via mma.m16n8k16 + ldmatrix.
// Y[4096, 256] = [x1;x2] @ [W1;W2]^T  (K-split 2 into a/b buffers).
// Grid (32 mT, 4 nT, 2 kS) = 256 CTAs, 256 threads = 8 warps (4m x 2n),
// CTA tile 128m x 64n, warp tile 32x32, K chunks of 64, cp.async dbl buffer.
// SMEM rows padded to 72 halves (144B): ldmatrix rows hit banks 4r..4r+3.
// ---------------------------------------------------------------------------
#define HSTR   72
#define A_ST_H (128 * HSTR)            // 9216 halves / stage
#define B_ST_H (64 * HSTR)             // 4608 halves / stage
#define SMEM_GEMM ((2 * A_ST_H + 2 * B_ST_H) * 2)   // 55296 bytes

__global__ void __launch_bounds__(256)
gemm_f16()
{
    extern __shared__ __align__(16) __half sh[];
    const uint32_t smbase = smem_u32(sh);

    const int tid = threadIdx.x;
    const int wid = tid >> 5, lane = tid & 31;
    const int g = lane >> 2, t = lane & 3;

    const int mT = blockIdx.x;              // 0..31
    const int nT = blockIdx.y;              // 0..3
    const int kS = blockIdx.z;              // 0..1
    const int hf = (mT >= 16) ? 1 : 0;
    const __half* __restrict__ X = hf ? g_x2h : g_x1h;
    const int rowLoc = (mT & 15) * 128;
    const int hBase  = nT * 64;
    const int kOff   = kS * 256;
    const int wOff   = (hf ? FEATF : 0) + kOff;

    const int mw = wid & 3;                 // m warp: 0..3 (x32)
    const int nw = wid >> 2;                // n warp: 0..1 (x32)

    // fill indexing
    const int fr = tid >> 3;                // 0..31 (row step below)
    const int fsg = tid & 7;                // 8-half segment

    auto loadA = [&](int s, int c) {
        const uint32_t base = smbase + s * A_ST_H * 2;
        #pragma unroll
        for (int q = 0; q < 4; q++) {
            int row = fr + q * 32;          // 0..127
            cp16(base + (row * HSTR + fsg * 8) * 2,
                 X + (size_t)(rowLoc + row) * FEATF + kOff + c * 64 + fsg * 8);
        }
    };
    auto loadB = [&](int s, int c) {
        const uint32_t base = smbase + (2 * A_ST_H + s * B_ST_H) * 2;
        #pragma unroll
        for (int q = 0; q < 2; q++) {
            int row = fr + q * 32;          // 0..63
            cp16(base + (row * HSTR + fsg * 8) * 2,
                 g_Wh + (size_t)(hBase + row) * (4 * HH) + wOff + c * 64 + fsg * 8);
        }
    };

    // ldmatrix per-thread address components
    const int aRow = lane & 15;                     // row within m16
    const int aCol = (lane & 16) ? 8 : 0;           // k offset
    const int bRow = (lane & 7) + ((lane & 16) ? 8 : 0);   // row within n16
    const int bCol = (lane & 8) ? 8 : 0;            // k offset

    float acc[2][4][4];                     // [mf(16)][nf(8)][reg]
    #pragma unroll
    for (int mf = 0; mf < 2; mf++)
        #pragma unroll
        for (int nf = 0; nf < 4; nf++)
            #pragma unroll
            for (int q = 0; q < 4; q++) acc[mf][nf][q] = 0.0f;

    loadA(0, 0); loadB(0, 0);
    asm volatile("cp.async.commit_group;" ::: "memory");

    const int NCH = 4;                      // 256 / 64
    for (int c = 0; c < NCH; c++) {
        if (c + 1 < NCH) {
            loadA((c + 1) & 1, c + 1);
            loadB((c + 1) & 1, c + 1);
            asm volatile("cp.async.commit_group;" ::: "memory");
            asm volatile("cp.async.wait_group 1;" ::: "memory");
        } else {
            asm volatile("cp.async.wait_group 0;" ::: "memory");
        }
        __syncthreads();

        const int s = c & 1;
        const uint32_t aStage = smbase + s * A_ST_H * 2;
        const uint32_t bStage = smbase + (2 * A_ST_H + s * B_ST_H) * 2;

        // A fragments: 2 mf x 4 kq, x4 ldmatrix each
        uint32_t a[2][4][4];
        #pragma unroll
        for (int mf = 0; mf < 2; mf++)
            #pragma unroll
            for (int kq = 0; kq < 4; kq++)
                ldsm_x4(a[mf][kq],
                        aStage + (((mw * 32 + mf * 16 + aRow) * HSTR) + kq * 16 + aCol) * 2);

        // B fragments: 2 n16-groups x 4 kq; regs [0,1]=b(nf even) [2,3]=b(nf odd)
        uint32_t b[2][4][4];
        #pragma unroll
        for (int q2 = 0; q2 < 2; q2++)
            #pragma unroll
            for (int kq = 0; kq < 4; kq++)
                ldsm_x4(b[q2][kq],
                        bStage + (((nw * 32 + q2 * 16 + bRow) * HSTR) + kq * 16 + bCol) * 2);

        #pragma unroll
        for (int kq = 0; kq < 4; kq++)
            #pragma unroll
            for (int mf = 0; mf < 2; mf++)
                #pragma unroll
                for (int nf = 0; nf < 4; nf++)
                    mma_f16(acc[mf][nf], a[mf][kq],
                            b[nf >> 1][kq][(nf & 1) * 2],
                            b[nf >> 1][kq][(nf & 1) * 2 + 1]);
        __syncthreads();
    }

    float* __restrict__ Y = hf ? (kS ? g_y2b : g_y2a)
                               : (kS ? g_y1b : g_y1a);
    #pragma unroll
    for (int mf = 0; mf < 2; mf++) {
        #pragma unroll
        for (int nf = 0; nf < 4; nf++) {
            const int row = rowLoc + mw * 32 + mf * 16 + g;
            const int h   = hBase + nw * 32 + nf * 8 + 2 * t;
            *(float2*)&Y[(size_t)row * HH + h]       = make_float2(acc[mf][nf][0], acc[mf][nf][1]);
            *(float2*)&Y[(size_t)(row + 8) * HH + h] = make_float2(acc[mf][nf][2], acc[mf][nf][3]);
        }
    }
}

// ---------------------------------------------------------------------------
// Pair reduction (partial over i-chunk of 16); sums K-split halves on load,
// bias folded into t2; scaled partial atomically added to out.
// Grid (8, 32, 4), 256 threads.
// ---------------------------------------------------------------------------
__global__ void __launch_bounds__(256)
pairsum_kernel(const int* __restrict__ sl1p, const int* __restrict__ sl2p,
               const float* __restrict__ bias, float* __restrict__ out)
{
    const int b  = blockIdx.y;
    const int hb = blockIdx.x;
    const int s  = blockIdx.z;
    const int tid = threadIdx.x;
    const int h  = tid & 31;
    const int jg = tid >> 5;

    const int sl1 = sl1p[b];
    const int sl2 = sl2p[b];
    const int i0  = s * 16;
    if (i0 >= sl1) return;

    __shared__ float y1s[16 * 32];
    {
        int i = tid >> 5, hh = tid & 31;
        int base0 = (b * LL1 + i0 + i)     * HH + hb * 32 + hh;
        int base1 = (b * LL1 + i0 + 8 + i) * HH + hb * 32 + hh;
        y1s[tid]       = g_y1a[base0] + g_y1b[base0];
        y1s[tid + 256] = g_y1a[base1] + g_y1b[base1];
    }
    __syncthreads();

    const float bh = bias[hb * 32 + h];
    float t2[8];
    #pragma unroll
    for (int k = 0; k < 8; k++) {
        int j = jg * 8 + k;
        int idx = (b * LL2 + j) * HH + hb * 32 + h;
        t2[k] = (j < sl2) ? (g_y2a[idx] + g_y2b[idx] + bh) : -INFINITY;
    }

    const int niter = min(16, sl1 - i0);
    float acc[8];
    #pragma unroll
    for (int k = 0; k < 8; k++) acc[k] = 0.0f;

    for (int i = 0; i < niter; i++) {
        float v = y1s[i * 32 + h];
        #pragma unroll
        for (int k = 0; k < 8; k++)
            acc[k] += fmaxf(v + t2[k], 0.0f);
    }

    float p = 0.0f;
    #pragma unroll
    for (int k = 0; k < 8; k++) p += acc[k];

    __shared__ float red[8][32];
    red[jg][h] = p;
    __syncthreads();
    if (jg == 0) {
        float ss = 0.0f;
        #pragma unroll
        for (int gg = 0; gg < 8; gg++) ss += red[gg][h];
        const float n = (float)(sl1 * sl2);
        atomicAdd(&out[b * HH + hb * 32 + h], ss / n);
    }
}

extern "C" void kernel_launch(void* const* d_in, const int* in_sizes, int n_in,
                              void* d_out, int out_size)
{
    const float* x1   = (const float*)d_in[0];
    const int*   sl1  = (const int*)  d_in[1];
    const float* x2   = (const float*)d_in[2];
    const int*   sl2  = (const int*)  d_in[3];
    const float* W    = (const float*)d_in[4];
    const float* bias = (const float*)d_in[5];
    float* out = (float*)d_out;

    cudaFuncSetAttribute(gemm_f16, cudaFuncAttributeMaxDynamicSharedMemorySize,
                         SMEM_GEMM);

    preconv_kernel<<<1153, 256>>>(x1, x2, W, sl1, sl2, bias, out);
    gemm_f16<<<dim3(32, 4, 2), 256, SMEM_GEMM>>>();
    pairsum_kernel<<<dim3(8, 32, 4), 256>>>(sl1, sl2, bias, out);
}